// round 8
// baseline (speedup 1.0000x reference)
#include <cuda_runtime.h>
#include <cuda_bf16.h>
#include <math.h>

// TemporalAttention: out[d,b] = sum_s softmax_s((enc[b,s,:]·We_w + We_b)*ut)[s] * enc[b,s,d]
// cp.async.bulk (TMA-engine) smem ring: one-instruction 16KB tile loads, mbarrier
// completion. MLP comes from ring depth, decoupled from registers/warps.
// Score phase is warp-uniform (shuffles unconditional; validity predicate only on
// the pbuf write) -- partial tail tiles cannot split a warp at a shfl.sync.
// Accum: thread t owns column d=t. Fused last-CTA-done split merge.

#define D_DIM     256
#define NSPLIT    19
#define THREADS   256
#define NBUF      4
#define T_ROWS    16
#define TILE_FLTS (T_ROWS * D_DIM)          // 4096 floats = 16KB
#define MAXB      128
#define MAXSPLIT  32

#define SMEM_BYTES (NBUF * TILE_FLTS * 4 + T_ROWS * 4 + NBUF * 8)

__device__ float        g_scratch[MAXB * MAXSPLIT * (D_DIM + 2)];
__device__ unsigned int g_cnt[MAXB];   // zero-init; reset by merger each launch

__device__ __forceinline__ unsigned su32(const void* p) {
    return (unsigned)__cvta_generic_to_shared(p);
}

#define MBAR_INIT(a, c) \
    asm volatile("mbarrier.init.shared.b64 [%0], %1;" :: "r"(a), "r"(c) : "memory")
#define MBAR_EXPECT_TX(a, bytes) \
    asm volatile("mbarrier.arrive.expect_tx.shared.b64 _, [%0], %1;" :: "r"(a), "r"(bytes) : "memory")
#define BULK_G2S(dst, src, bytes, mbar) \
    asm volatile("cp.async.bulk.shared::cta.global.mbarrier::complete_tx::bytes [%0], [%1], %2, [%3];" \
                 :: "r"(dst), "l"(src), "r"(bytes), "r"(mbar) : "memory")

__device__ __forceinline__ void mbar_wait(unsigned mbar, unsigned parity) {
    asm volatile(
        "{\n\t"
        ".reg .pred P1;\n\t"
        "WAIT_%=:\n\t"
        "mbarrier.try_wait.parity.acquire.cta.shared::cta.b64 P1, [%0], %1, 0x989680;\n\t"
        "@P1 bra DONE_%=;\n\t"
        "bra WAIT_%=;\n\t"
        "DONE_%=:\n\t"
        "}"
        :: "r"(mbar), "r"(parity) : "memory");
}

__global__ __launch_bounds__(THREADS, 3) void ta_fused(
    const float* __restrict__ enc,
    const float* __restrict__ Ww,
    const float* __restrict__ Wb,
    const float* __restrict__ ut,
    float* __restrict__ out,
    int S, int B)
{
    extern __shared__ float smem[];
    float* bufs = smem;                               // NBUF * 4096 floats
    float* pbuf = smem + NBUF * TILE_FLTS;            // 16 floats
    unsigned long long* mbar = (unsigned long long*)(pbuf + T_ROWS);  // NBUF barriers

    const int split = blockIdx.x;
    const int b     = blockIdx.y;
    const int t     = threadIdx.x;
    const int row   = t >> 4;     // 0..15: score row within tile
    const int part  = t & 15;     // 16 threads per row

    // Thread's score columns: float4 index part + j*16 (conflict-free LDS.128)
    float4 wv[4];
#pragma unroll
    for (int j = 0; j < 4; j++) wv[j] = ((const float4*)Ww)[part + j * 16];
    const float be = Wb[0];
    const float u  = ut[0];

    const int s0   = (int)(((long long)split * S) / NSPLIT);
    const int s1   = (int)(((long long)(split + 1) * S) / NSPLIT);
    const int rows = s1 - s0;
    const float* base = enc + ((long long)b * S + s0) * D_DIM;

    const int ntiles = (rows + T_ROWS - 1) / T_ROWS;

    if (t == 0) {
#pragma unroll
        for (int i = 0; i < NBUF; i++) MBAR_INIT(su32(mbar + i), 1);
    }
    __syncthreads();

    // Prime the ring
    if (t == 0) {
        int pn = ntiles < NBUF ? ntiles : NBUF;
        for (int i = 0; i < pn; i++) {
            int rv = min(T_ROWS, rows - i * T_ROWS);
            unsigned bytes = (unsigned)rv * D_DIM * 4u;
            unsigned mb = su32(mbar + i);
            MBAR_EXPECT_TX(mb, bytes);
            BULK_G2S(su32(bufs + i * TILE_FLTS),
                     base + (long long)i * T_ROWS * D_DIM, bytes, mb);
        }
    }

    float acc = 0.0f;   // this thread's d = t column
    float l   = 0.0f;

    for (int k = 0; k < ntiles; k++) {
        mbar_wait(su32(mbar + (k & (NBUF - 1))), (k / NBUF) & 1);

        float* buf = bufs + (k & (NBUF - 1)) * TILE_FLTS;
        const int rv = min(T_ROWS, rows - k * T_ROWS);

        // ---- score phase: 16 threads per row, warp-uniform ----
        // All threads load + reduce unconditionally (invalid rows read stale smem,
        // harmless); validity gates only the pbuf write. No divergent shfl.sync.
        {
            const float4* rp = (const float4*)(buf + row * D_DIM);
            float d = 0.0f;
#pragma unroll
            for (int j = 0; j < 4; j++) {
                float4 x = rp[part + j * 16];
                d = fmaf(x.x, wv[j].x, fmaf(x.y, wv[j].y,
                    fmaf(x.z, wv[j].z, fmaf(x.w, wv[j].w, d))));
            }
            d += __shfl_xor_sync(0xffffffffu, d, 1);
            d += __shfl_xor_sync(0xffffffffu, d, 2);
            d += __shfl_xor_sync(0xffffffffu, d, 4);
            d += __shfl_xor_sync(0xffffffffu, d, 8);
            if (part == 0) pbuf[row] = (row < rv) ? __expf((d + be) * u) : 0.0f;
        }
        __syncthreads();   // pbuf ready

        // ---- accum phase: thread t owns column d = t ----
        const float* col = buf + t;
        if (rv == T_ROWS) {
            float4 pv[4];
#pragma unroll
            for (int j = 0; j < 4; j++) pv[j] = ((const float4*)pbuf)[j];
#pragma unroll
            for (int j = 0; j < 4; j++) {
                acc = fmaf(pv[j].x, col[(j * 4 + 0) * D_DIM], acc);
                acc = fmaf(pv[j].y, col[(j * 4 + 1) * D_DIM], acc);
                acc = fmaf(pv[j].z, col[(j * 4 + 2) * D_DIM], acc);
                acc = fmaf(pv[j].w, col[(j * 4 + 3) * D_DIM], acc);
                l += (pv[j].x + pv[j].y) + (pv[j].z + pv[j].w);
            }
        } else {
            for (int s = 0; s < rv; s++) {
                float p = pbuf[s];
                acc = fmaf(p, col[s * D_DIM], acc);
                l += p;
            }
        }
        __syncthreads();   // buffer k fully consumed

        // ---- refill the buffer just freed ----
        if (t == 0 && k + NBUF < ntiles) {
            int i = k + NBUF;
            int rv2 = min(T_ROWS, rows - i * T_ROWS);
            unsigned bytes = (unsigned)rv2 * D_DIM * 4u;
            unsigned mb = su32(mbar + (i & (NBUF - 1)));
            MBAR_EXPECT_TX(mb, bytes);
            BULK_G2S(su32(bufs + (i & (NBUF - 1)) * TILE_FLTS),
                     base + (long long)i * T_ROWS * D_DIM, bytes, mb);
        }
    }

    // ---- write partial for this (b, split): acc is already the full column ----
    float* o = g_scratch + ((long long)(b * NSPLIT + split)) * (D_DIM + 2);
    o[t] = acc;
    if (t == 0) o[D_DIM] = l;   // all threads hold identical l

    // ---- fused split-merge: last CTA per batch sums all NSPLIT partials ----
    __threadfence();
    __syncthreads();
    __shared__ unsigned int s_last;
    if (t == 0) s_last = (atomicAdd(&g_cnt[b], 1u) == (unsigned)(NSPLIT - 1));
    __syncthreads();
    if (!s_last) return;

    const float* sc = g_scratch + (long long)b * NSPLIT * (D_DIM + 2);
    float Lg = 0.0f, ag = 0.0f;
#pragma unroll
    for (int i = 0; i < NSPLIT; i++) {
        Lg += sc[i * (D_DIM + 2) + D_DIM];
        ag += sc[i * (D_DIM + 2) + t];
    }
    out[t * B + b] = ag / Lg;   // out is [D, B]

    if (t == 0) g_cnt[b] = 0;   // reset for next graph replay
}

extern "C" void kernel_launch(void* const* d_in, const int* in_sizes, int n_in,
                              void* d_out, int out_size)
{
    const float* enc = (const float*)d_in[0];
    const float* Ww  = (const float*)d_in[1];
    const float* Wb  = (const float*)d_in[2];
    const float* ut  = (const float*)d_in[3];
    float* out = (float*)d_out;

    const int D = in_sizes[1];           // 256
    const int B = out_size / D;          // 64
    const int S = in_sizes[0] / (B * D); // 4096

    cudaFuncSetAttribute(ta_fused, cudaFuncAttributeMaxDynamicSharedMemorySize, SMEM_BYTES);

    dim3 grid(NSPLIT, B);
    ta_fused<<<grid, THREADS, SMEM_BYTES>>>(enc, Ww, Wb, ut, out, S, B);
}